// round 17
// baseline (speedup 1.0000x reference)
#include <cuda_runtime.h>
#include <cuda_fp16.h>
#include <cstdint>

#define NPIX 65536
#define DDIM 256
#define KCODES 512
#define MT 128
#define THREADS 512
// smem float offsets
#define AF_OFF    0        // afrag: 8 mtiles x 16 ks x 32 lanes x uint4 = 16384 floats
#define STAGE_OFF 16384    // stage 32 x 132 = 4224 floats; cand overlays post-mainloop
#define CD_OFF    16384    // cand_d [16][128]
#define CI_OFF    18432    // cand_i [16][128]
#define ZSQP_OFF  20608    // 4 x 128 partials
#define ZSQ_OFF   21120    // 128
#define ESQ_OFF   21248    // 512
#define SMEM_FLOATS 21760  // 87,040 bytes -> 2 CTAs/SM, ~54KB L1D left for B stream
#define EPS 2e-4f          // rescue window (fp16 filter dist err ~1.4e-5 rms)

__device__ float g_esq[KCODES];
// B fragments (fp16): [sup(16)][ks(16)][nt4(4)][lane(32)][b0,b1] u32 = 256KB
__device__ __align__(16) unsigned int e_frag[65536];

static __device__ __forceinline__ uint32_t smem_u32(const void* p) {
    uint32_t a;
    asm("{ .reg .u64 t; cvta.to.shared.u64 t, %1; cvt.u32.u64 %0, t; }" : "=r"(a) : "l"(p));
    return a;
}
// pack two f32 -> f16x2; SECOND operand lands in lower 16 bits (k-even)
static __device__ __forceinline__ uint32_t f16pack(float hi, float lo) {
    uint32_t r;
    asm("cvt.rn.f16x2.f32 %0, %1, %2;" : "=r"(r) : "f"(hi), "f"(lo));
    return r;
}
static __device__ __forceinline__ void mma_fp16(float* c, const uint32_t* a,
                                                uint32_t b0, uint32_t b1) {
    asm volatile("mma.sync.aligned.m16n8k16.row.col.f32.f16.f16.f32 "
                 "{%0,%1,%2,%3}, {%4,%5,%6,%7}, {%8,%9}, {%0,%1,%2,%3};"
                 : "+f"(c[0]), "+f"(c[1]), "+f"(c[2]), "+f"(c[3])
                 : "r"(a[0]), "r"(a[1]), "r"(a[2]), "r"(a[3]), "r"(b0), "r"(b1));
}

// ---- prep: scatter codebook into fp16 B-fragment image + esq (exact reference order) ----
__global__ void prep_kernel(const float* __restrict__ cb) {
    __shared__ float part[4];
    const int n = blockIdx.x;
    const int t = threadIdx.x;
    const int d = t * 2;
    const int g = n & 7, nt4 = (n >> 3) & 3, sup = n >> 5;

    float v0 = cb[n * DDIM + d];
    float v1 = cb[n * DDIM + d + 1];
    uint32_t pk = f16pack(v1, v0);          // lower 16 = k-even
    int ks   = d >> 4;                      // 0..15
    int ko   = d & 15;
    int half = ko >> 3;
    int tig  = (ko >> 1) & 3;
    int lane = g * 4 + tig;
    e_frag[((((sup * 16 + ks) * 4 + nt4) * 32) + lane) * 2 + half] = pk;

    if (t < 4) {
        float s = 0.f;
        for (int i = 0; i < DDIM / 4; i++) {
            float x = cb[n * DDIM + i * 4 + t];
            s = __fadd_rn(s, __fmul_rn(x, x));
        }
        part[t] = s;
    }
    __syncthreads();
    if (t == 0)
        g_esq[n] = __fadd_rn(__fadd_rn(part[0], part[1]), __fadd_rn(part[2], part[3]));
}

__global__ __launch_bounds__(THREADS, 2)
void vq_mma_kernel(const float* __restrict__ z, const float* __restrict__ cb,
                   float* __restrict__ out) {
    extern __shared__ __align__(16) float smem[];
    uint32_t*  afrag  = (uint32_t*)(smem + AF_OFF);
    float*     stage  = smem + STAGE_OFF;
    float*     zsqp   = smem + ZSQP_OFF;
    float*     zsq_s  = smem + ZSQ_OFF;
    float*     esq_s  = smem + ESQ_OFF;
    float*     cand_d = smem + CD_OFF;
    int*       cand_i = (int*)(smem + CI_OFF);

    const int tid  = threadIdx.x;
    const int warp = tid >> 5;
    const int lane = tid & 31;
    const int g    = lane >> 2;      // 0..7
    const int tig  = lane & 3;       // 0..3
    const int wm   = warp & 7;       // M-warp -> mtile wm (16 px)
    const int wn   = warp >> 3;      // N-warp -> nt4 {wn*2, wn*2+1}

    const int pix_base = blockIdx.x * MT;
    const float* zbase = z + (size_t)(pix_base >> 10) * (DDIM * 1024) + (pix_base & 1023);

    esq_s[tid] = g_esq[tid];

    // ---- prologue: per 32-d block, stage z then build afrag + zsq partials ----
    {
        const int p_z  = tid & 127;          // zsq pixel
        const int j_z  = tid >> 7;           // zsq mod-4 lane
        float s_z = 0.f;
        const int ksl = (tid >> 5) & 1;      // local ks within 32-d block
        const int mti = tid >> 6;            // 0..7
        const int k0l = ksl * 16 + 2 * tig;  // local d of k-pair start
        const int r0  = mti * 16 + g;
        const int r1  = r0 + 8;

        for (int db = 0; db < 8; db++) {
            __syncthreads();
#pragma unroll
            for (int it = 0; it < 2; it++) {
                int linear = tid + THREADS * it;        // 0..1023 float4
                int dd = linear >> 5;                   // 0..31
                int p4 = (linear & 31) << 2;            // 0..124
                float4 v = *(const float4*)(zbase + (size_t)(db * 32 + dd) * 1024 + p4);
                *(float4*)(stage + dd * 132 + p4) = v;
            }
            __syncthreads();
            {
                float s00 = stage[(k0l)     * 132 + r0];
                float s01 = stage[(k0l + 1) * 132 + r0];
                float s10 = stage[(k0l)     * 132 + r1];
                float s11 = stage[(k0l + 1) * 132 + r1];
                float s02 = stage[(k0l + 8) * 132 + r0];
                float s03 = stage[(k0l + 9) * 132 + r0];
                float s12 = stage[(k0l + 8) * 132 + r1];
                float s13 = stage[(k0l + 9) * 132 + r1];
                uint4 a;
                a.x = f16pack(s01, s00);
                a.y = f16pack(s11, s10);
                a.z = f16pack(s03, s02);
                a.w = f16pack(s13, s12);
                const int ksg = db * 2 + ksl;           // global ks 0..15
                *(uint4*)(afrag + ((mti * 16 + ksg) * 32 + lane) * 4) = a;
            }
#pragma unroll
            for (int i = 0; i < 8; i++) {
                float x = stage[(j_z + 4 * i) * 132 + p_z];
                s_z = __fadd_rn(s_z, __fmul_rn(x, x));
            }
        }
        __syncthreads();
        zsqp[j_z * 128 + p_z] = s_z;
    }
    __syncthreads();
    if (tid < MT)
        zsq_s[tid] = __fadd_rn(__fadd_rn(zsqp[tid], zsqp[128 + tid]),
                               __fadd_rn(zsqp[256 + tid], zsqp[384 + tid]));
    __syncthreads();   // afrag + zsq_s visible to all warps; no more barriers until epilogue

    // per-slot best2: slot s = pixel-half (0: px0, 1: px0+8)
    float d1[2], d2[2];
    int   i1[2], i2[2];
    float acc[2][4];
#pragma unroll
    for (int s = 0; s < 2; s++) { d1[s] = 3.4e38f; d2[s] = 3.4e38f; i1[s] = 0; i2[s] = 0; }
#pragma unroll
    for (int j = 0; j < 2; j++)
#pragma unroll
        for (int r = 0; r < 4; r++) acc[j][r] = 0.f;

    const uint32_t* afw = afrag + (wm * 16) * 32 * 4;   // this warp's mtile
    const int px0 = wm * 16 + g;
    const float zq0 = zsq_s[px0];
    const float zq1 = zsq_s[px0 + 8];

    // ---- free-running mainloop: B streamed from gmem (L1/L2), zero barriers ----
    for (int s = 0; s < 16; s++) {       // 16 supers x 32 codes
        const unsigned int* bs = e_frag + s * 4096 + ((wn * 2) * 32 + lane) * 2;
#pragma unroll
        for (int ks = 0; ks < 16; ks++) {
            uint4 av = *(const uint4*)(afw + (ks * 32 + lane) * 4);
            uint32_t a4[4] = {av.x, av.y, av.z, av.w};
            uint2 b0 = __ldg((const uint2*)(bs + (ks * 4) * 64));
            uint2 b1 = __ldg((const uint2*)(bs + (ks * 4 + 1) * 64));
            mma_fp16(acc[0], a4, b0.x, b0.y);
            mma_fp16(acc[1], a4, b1.x, b1.y);
        }

        // ---- fold this super's 32 codes into per-slot best2 ----
#pragma unroll
        for (int j = 0; j < 2; j++) {
            const int c0 = s * 32 + (wn * 2 + j) * 8 + 2 * tig;
            const float e0 = esq_s[c0], e1 = esq_s[c0 + 1];
            float dd[4];
            dd[0] = (zq0 - 2.f * acc[j][0]) + e0;
            dd[1] = (zq0 - 2.f * acc[j][1]) + e1;
            dd[2] = (zq1 - 2.f * acc[j][2]) + e0;
            dd[3] = (zq1 - 2.f * acc[j][3]) + e1;
#pragma unroll
            for (int q = 0; q < 4; q++) {
                const int sl = q >> 1;
                const int c = c0 + (q & 1);
                const float d = dd[q];
                if (d < d2[sl]) {
                    if (d < d1[sl]) { d2[sl] = d1[sl]; i2[sl] = i1[sl]; d1[sl] = d; i1[sl] = c; }
                    else            { d2[sl] = d;      i2[sl] = c; }
                }
                acc[j][q] = 0.f;
            }
        }
    }

    // ---- dump 16 candidates per pixel (8 (wn,tig) slots x best2) ----
    __syncthreads();   // stage dead; cand overlay safe only after all warps pass prologue
#pragma unroll
    for (int s = 0; s < 2; s++) {
        const int px = wm * 16 + g + s * 8;
        const int sl = (wn * 4 + tig) * 2;
        cand_d[sl * 128 + px]       = d1[s];
        cand_i[sl * 128 + px]       = i1[s];
        cand_d[(sl + 1) * 128 + px] = d2[s];
        cand_i[(sl + 1) * 128 + px] = i2[s];
    }
    __syncthreads();

    // ---- exact rescore within EPS of mma-min (R4-proven ascending-d fmaf order) ----
    if (tid < MT) {
        float mn = 3.4e38f;
#pragma unroll
        for (int s = 0; s < 16; s++) {
            float ad = cand_d[s * 128 + tid];
            if (ad < mn) mn = ad;
        }
        const float zq = zsq_s[tid];
        const float* zg = zbase + tid;      // z[px=tid][d] at stride 1024 (L2-resident)
        float bestd = 3.4e38f;
        int   besti = 1 << 30;
#pragma unroll 1
        for (int s = 0; s < 16; s++) {
            float ad = cand_d[s * 128 + tid];
            if (ad < mn + EPS) {
                int c = cand_i[s * 128 + tid];
                const float* er = cb + (size_t)c * DDIM;
                float a = 0.f;
#pragma unroll 8
                for (int d = 0; d < DDIM; d++)
                    a = fmaf(zg[(size_t)d << 10], __ldg(er + d), a);
                float dist = __fadd_rn(__fadd_rn(zq, -2.f * a), esq_s[c]);
                if (dist < bestd || (dist == bestd && c < besti)) { bestd = dist; besti = c; }
            }
        }
        out[pix_base + tid] = (float)besti;
    }
}

extern "C" void kernel_launch(void* const* d_in, const int* in_sizes, int n_in,
                              void* d_out, int out_size) {
    const float* a0 = (const float*)d_in[0];
    const float* a1 = (const float*)d_in[1];
    const float* z  = (in_sizes[0] > in_sizes[1]) ? a0 : a1;
    const float* cb = (in_sizes[0] > in_sizes[1]) ? a1 : a0;
    float* out = (float*)d_out;

    cudaFuncSetAttribute(vq_mma_kernel,
                         cudaFuncAttributeMaxDynamicSharedMemorySize,
                         SMEM_FLOATS * 4);

    prep_kernel<<<KCODES, DDIM / 2>>>(cb);
    vq_mma_kernel<<<NPIX / MT, THREADS, SMEM_FLOATS * 4>>>(z, cb, out);
}